// round 1
// baseline (speedup 1.0000x reference)
#include <cuda_runtime.h>

#define FULLMASK 0xFFFFFFFFu

// One warp per (b,c) row of T elements. Row is processed in tiles of 128
// elements (one float4 per lane). Linear-recurrence scan:
//   y[p] = g*y[p-1] + (1-g)*x[p]
// reassociated as: per-lane local scan (4 elems) -> warp Kogge-Stone scan of
// lane tails with ratio g^4 -> cross-tile carry with g^128.
__global__ void __launch_bounds__(256, 4)
ema_scan_kernel(const float* __restrict__ x,
                const float* __restrict__ w,
                float* __restrict__ out,
                int Cdim, int T, int nrows)
{
    const int warp = threadIdx.x >> 5;
    const int lane = threadIdx.x & 31;
    const int row  = blockIdx.x * 8 + warp;
    if (row >= nrows) return;

    const float g = __ldg(&w[row % Cdim]);

    // powers of g
    const float g1   = g;
    const float g2   = g * g;
    const float g3   = g2 * g;
    const float g4   = g2 * g2;      // ratio per lane step
    const float g8   = g4 * g4;
    const float g16  = g8 * g8;
    const float g32  = g16 * g16;
    const float g64  = g32 * g32;
    const float g128 = g64 * g64;    // ratio per tile step

    // g^(4*lane) by binary decomposition (exact products, no powf)
    float pl = 1.0f;
    if (lane & 1)  pl *= g4;
    if (lane & 2)  pl *= g8;
    if (lane & 4)  pl *= g16;
    if (lane & 8)  pl *= g32;
    if (lane & 16) pl *= g64;

    const float omg = 1.0f - g;

    const float4* __restrict__ xin  = (const float4*)(x   + (size_t)row * T);
    float4*       __restrict__ yout = (float4*)      (out + (size_t)row * T);

    const int ntiles = T >> 7;   // 128 elements per tile
    float C = 0.0f;              // running EMA value at last elem of prev tile

    float4 cur = xin[lane];      // prefetch tile 0

    for (int t = 0; t < ntiles; ++t) {
        // prefetch next tile while we chew on this one
        float4 nxt = cur;
        if (t + 1 < ntiles) nxt = xin[(t + 1) * 32 + lane];

        // per-lane local scan of 4 contiguous elements
        const float u0 = cur.x * omg;
        const float u1 = cur.y * omg;
        const float u2 = cur.z * omg;
        const float u3 = cur.w * omg;
        const float l0 = u0;
        const float l1 = fmaf(g, l0, u1);
        const float l2 = fmaf(g, l1, u2);
        const float l3 = fmaf(g, l2, u3);

        // warp inclusive scan of lane tails, ratio r = g^4:
        // v_lane = sum_{q<=lane} r^(lane-q) * l3_q
        float v = l3;
        float tv;
        tv = __shfl_up_sync(FULLMASK, v, 1);  if (lane >= 1)  v = fmaf(g4,  tv, v);
        tv = __shfl_up_sync(FULLMASK, v, 2);  if (lane >= 2)  v = fmaf(g8,  tv, v);
        tv = __shfl_up_sync(FULLMASK, v, 4);  if (lane >= 4)  v = fmaf(g16, tv, v);
        tv = __shfl_up_sync(FULLMASK, v, 8);  if (lane >= 8)  v = fmaf(g32, tv, v);
        tv = __shfl_up_sync(FULLMASK, v, 16); if (lane >= 16) v = fmaf(g64, tv, v);

        // exclusive carry into this lane from earlier lanes of the tile
        float carryL = __shfl_up_sync(FULLMASK, v, 1);
        if (lane == 0) carryL = 0.0f;

        // W = EMA value at position (4*lane - 1) of this tile, including the
        // cross-tile carry C at position -1: W = carryL + g^(4*lane) * C
        const float W = fmaf(pl, C, carryL);

        float4 yo;
        yo.x = fmaf(g1, W, l0);
        yo.y = fmaf(g2, W, l1);
        yo.z = fmaf(g3, W, l2);
        yo.w = fmaf(g4, W, l3);
        yout[t * 32 + lane] = yo;

        // cross-tile carry: y at tile's last position
        const float v31 = __shfl_sync(FULLMASK, v, 31);
        C = fmaf(g128, C, v31);

        cur = nxt;
    }
}

extern "C" void kernel_launch(void* const* d_in, const int* in_sizes, int n_in,
                              void* d_out, int out_size)
{
    const float* x = (const float*)d_in[0];
    const float* w = (const float*)d_in[1];
    float* out = (float*)d_out;

    const int Cdim = in_sizes[1];          // 512
    const int T    = 16384;                // fixed problem shape
    const int nrows = in_sizes[0] / T;     // B*C = 4096

    const int warps_per_block = 8;
    dim3 block(32 * warps_per_block);
    dim3 grid((nrows + warps_per_block - 1) / warps_per_block);
    ema_scan_kernel<<<grid, block>>>(x, w, out, Cdim, T, nrows);
}

// round 2
// speedup vs baseline: 1.2038x; 1.2038x over previous
#include <cuda_runtime.h>

#define FULLMASK 0xFFFFFFFFu

// One warp per 2048-element SEGMENT of a (b,c) row. Segments are made
// independent by a warm-up halo: the warp starts its scan WARM elements
// before its segment with y=0 and discards the warm-up outputs. Since the
// recurrence ratio is g (=0.9 here), state decays as g^k; with a halo chosen
// so g^halo < 1e-10 the result is exact at fp32. Halo length is derived from
// g at runtime; if g is ~1 (or invalid) the halo clamps to the row start,
// degenerating to an exact full-prefix scan.
//
// Within a tile of 128 elements (float4 per lane):
//   per-lane 4-elem local scan -> warp Kogge-Stone scan of lane tails
//   (ratio g^4) -> cross-tile carry with g^128.
__global__ void __launch_bounds__(256, 5)
ema_scan_seg_kernel(const float* __restrict__ x,
                    const float* __restrict__ w,
                    float* __restrict__ out,
                    int Cdim, int T, int nrows, int nseg)
{
    const int SEG_TILES = 16;                 // 2048 elements per segment
    const int warp = threadIdx.x >> 5;
    const int lane = threadIdx.x & 31;
    const int gw   = blockIdx.x * 8 + warp;   // global segment id
    const int row  = gw / nseg;
    const int seg  = gw - row * nseg;
    if (row >= nrows) return;

    const float g = __ldg(&w[row % Cdim]);

    // warm-up tiles so that g^(128*wt) < 1e-10 (clamped to row start)
    int wt;
    if (g > 0.0f && g < 0.9999f) {
        const float we = -23.03f / __logf(g);          // elements
        wt = (int)(we * (1.0f / 128.0f)) + 1;          // tiles (ceil-ish)
    } else {
        wt = 0x3fffffff;                               // force exact fallback
    }
    const int seg_tile0 = seg * SEG_TILES;
    if (wt > seg_tile0) wt = seg_tile0;
    if (wt < 0) wt = 0;

    // powers of g
    const float g1   = g;
    const float g2   = g * g;
    const float g3   = g2 * g;
    const float g4   = g2 * g2;
    const float g8   = g4 * g4;
    const float g16  = g8 * g8;
    const float g32  = g16 * g16;
    const float g64  = g32 * g32;
    const float g128 = g64 * g64;

    // g^(4*lane) by binary decomposition
    float pl = 1.0f;
    if (lane & 1)  pl *= g4;
    if (lane & 2)  pl *= g8;
    if (lane & 4)  pl *= g16;
    if (lane & 8)  pl *= g32;
    if (lane & 16) pl *= g64;

    const float omg = 1.0f - g;

    const float4* __restrict__ xin  = (const float4*)(x   + (size_t)row * T);
    float4*       __restrict__ yout = (float4*)      (out + (size_t)row * T);

    const int tile_begin = seg_tile0 - wt;       // first (warm-up) tile
    const int count      = wt + SEG_TILES;       // total tiles this warp runs

    float C = 0.0f;
    float4 cur = xin[tile_begin * 32 + lane];    // prefetch first tile

    for (int t = 0; t < count; ++t) {
        float4 nxt = cur;
        if (t + 1 < count) nxt = xin[(tile_begin + t + 1) * 32 + lane];

        // per-lane local scan of 4 contiguous elements
        const float u0 = cur.x * omg;
        const float u1 = cur.y * omg;
        const float u2 = cur.z * omg;
        const float u3 = cur.w * omg;
        const float l0 = u0;
        const float l1 = fmaf(g, l0, u1);
        const float l2 = fmaf(g, l1, u2);
        const float l3 = fmaf(g, l2, u3);

        // warp inclusive scan of lane tails, ratio g^4
        float v = l3;
        float tv;
        tv = __shfl_up_sync(FULLMASK, v, 1);  if (lane >= 1)  v = fmaf(g4,  tv, v);
        tv = __shfl_up_sync(FULLMASK, v, 2);  if (lane >= 2)  v = fmaf(g8,  tv, v);
        tv = __shfl_up_sync(FULLMASK, v, 4);  if (lane >= 4)  v = fmaf(g16, tv, v);
        tv = __shfl_up_sync(FULLMASK, v, 8);  if (lane >= 8)  v = fmaf(g32, tv, v);
        tv = __shfl_up_sync(FULLMASK, v, 16); if (lane >= 16) v = fmaf(g64, tv, v);

        // exclusive carry from earlier lanes of this tile
        float carryL = __shfl_up_sync(FULLMASK, v, 1);
        if (lane == 0) carryL = 0.0f;

        // EMA value just before this lane's first element
        const float W = fmaf(pl, C, carryL);

        if (t >= wt) {
            float4 yo;
            yo.x = fmaf(g1, W, l0);
            yo.y = fmaf(g2, W, l1);
            yo.z = fmaf(g3, W, l2);
            yo.w = fmaf(g4, W, l3);
            yout[(tile_begin + t) * 32 + lane] = yo;
        }

        // cross-tile carry
        const float v31 = __shfl_sync(FULLMASK, v, 31);
        C = fmaf(g128, C, v31);

        cur = nxt;
    }
}

extern "C" void kernel_launch(void* const* d_in, const int* in_sizes, int n_in,
                              void* d_out, int out_size)
{
    const float* x = (const float*)d_in[0];
    const float* w = (const float*)d_in[1];
    float* out = (float*)d_out;

    const int Cdim  = in_sizes[1];          // 512
    const int T     = 16384;                // fixed problem shape
    const int nrows = in_sizes[0] / T;      // B*C = 4096
    const int nseg  = T / 2048;             // 8 segments per row

    const int total_warps     = nrows * nseg;
    const int warps_per_block = 8;
    dim3 block(32 * warps_per_block);
    dim3 grid((total_warps + warps_per_block - 1) / warps_per_block);
    ema_scan_seg_kernel<<<grid, block>>>(x, w, out, Cdim, T, nrows, nseg);
}

// round 3
// speedup vs baseline: 1.2098x; 1.0050x over previous
#include <cuda_runtime.h>

#define FULLMASK 0xFFFFFFFFu

// One warp per 4096-element SEGMENT of a (b,c) row, made independent via a
// decayed warm-up halo (g^halo below fp32 noise; exact-fallback clamp to row
// start if g ~ 1). Tile = 256 elements: each lane owns 8 contiguous elements
// (two adjacent float4s). Scan structure:
//   per-lane 8-elem local scan -> warp Kogge-Stone over lane tails with
//   ratio g^8 (5 shuffles per 256 elems) -> cross-tile carry with g^256.
__global__ void __launch_bounds__(256, 5)
ema_scan_seg256_kernel(const float* __restrict__ x,
                       const float* __restrict__ w,
                       float* __restrict__ out,
                       int Cdim, int T, int nrows, int nseg)
{
    const int SEG_TILES = 16;                 // 16 * 256 = 4096 elems/segment
    const int warp = threadIdx.x >> 5;
    const int lane = threadIdx.x & 31;
    const int gw   = blockIdx.x * 8 + warp;   // global segment id
    const int row  = gw / nseg;
    const int seg  = gw - row * nseg;
    if (row >= nrows) return;

    const float g = __ldg(&w[row % Cdim]);

    // warm-up tiles: need g^(256*wt) < 1e-10 (clamped to row start)
    int wt;
    if (g > 0.0f && g < 0.9999f) {
        const float we = -23.03f / __logf(g);          // elements of decay
        wt = (int)(we * (1.0f / 256.0f)) + 1;          // tiles
    } else {
        wt = 0x3fffffff;                               // exact fallback
    }
    const int seg_tile0 = seg * SEG_TILES;
    if (wt > seg_tile0) wt = seg_tile0;
    if (wt < 0) wt = 0;

    // powers of g
    const float g1 = g;
    const float g2 = g1 * g1;
    const float g3 = g2 * g1;
    const float g4 = g2 * g2;
    const float g5 = g4 * g1;
    const float g6 = g4 * g2;
    const float g7 = g4 * g3;
    const float g8 = g4 * g4;        // lane-step ratio
    const float g16  = g8  * g8;
    const float g32  = g16 * g16;
    const float g64  = g32 * g32;
    const float g128 = g64 * g64;
    const float g256 = g128 * g128;  // tile-step ratio

    // g^(8*lane) by binary decomposition
    float pl = 1.0f;
    if (lane & 1)  pl *= g8;
    if (lane & 2)  pl *= g16;
    if (lane & 4)  pl *= g32;
    if (lane & 8)  pl *= g64;
    if (lane & 16) pl *= g128;

    const float omg = 1.0f - g;

    const float4* __restrict__ xin  = (const float4*)(x   + (size_t)row * T);
    float4*       __restrict__ yout = (float4*)      (out + (size_t)row * T);

    const int tile_begin = seg_tile0 - wt;
    const int count      = wt + SEG_TILES;

    float C = 0.0f;

    // prefetch first tile: lane owns float4s (2*lane) and (2*lane+1)
    float4 curA = xin[tile_begin * 64 + 2 * lane];
    float4 curB = xin[tile_begin * 64 + 2 * lane + 1];

    for (int t = 0; t < count; ++t) {
        float4 nxtA = curA, nxtB = curB;
        if (t + 1 < count) {
            const int base = (tile_begin + t + 1) * 64 + 2 * lane;
            nxtA = xin[base];
            nxtB = xin[base + 1];
        }

        // per-lane local scan of 8 contiguous elements
        const float l0 = curA.x * omg;
        const float l1 = fmaf(g1, l0, curA.y * omg);
        const float l2 = fmaf(g1, l1, curA.z * omg);
        const float l3 = fmaf(g1, l2, curA.w * omg);
        const float l4 = fmaf(g1, l3, curB.x * omg);
        const float l5 = fmaf(g1, l4, curB.y * omg);
        const float l6 = fmaf(g1, l5, curB.z * omg);
        const float l7 = fmaf(g1, l6, curB.w * omg);

        // warp inclusive scan of lane tails, ratio g^8
        float v = l7;
        float tv;
        tv = __shfl_up_sync(FULLMASK, v, 1);  if (lane >= 1)  v = fmaf(g8,   tv, v);
        tv = __shfl_up_sync(FULLMASK, v, 2);  if (lane >= 2)  v = fmaf(g16,  tv, v);
        tv = __shfl_up_sync(FULLMASK, v, 4);  if (lane >= 4)  v = fmaf(g32,  tv, v);
        tv = __shfl_up_sync(FULLMASK, v, 8);  if (lane >= 8)  v = fmaf(g64,  tv, v);
        tv = __shfl_up_sync(FULLMASK, v, 16); if (lane >= 16) v = fmaf(g128, tv, v);

        // exclusive carry from earlier lanes of this tile
        float carryL = __shfl_up_sync(FULLMASK, v, 1);
        if (lane == 0) carryL = 0.0f;

        // EMA value just before this lane's first element
        const float W = fmaf(pl, C, carryL);

        if (t >= wt) {
            float4 yoA, yoB;
            yoA.x = fmaf(g1, W, l0);
            yoA.y = fmaf(g2, W, l1);
            yoA.z = fmaf(g3, W, l2);
            yoA.w = fmaf(g4, W, l3);
            yoB.x = fmaf(g5, W, l4);
            yoB.y = fmaf(g6, W, l5);
            yoB.z = fmaf(g7, W, l6);
            yoB.w = fmaf(g8, W, l7);
            const int obase = (tile_begin + t) * 64 + 2 * lane;
            yout[obase]     = yoA;
            yout[obase + 1] = yoB;
        }

        // cross-tile carry
        const float v31 = __shfl_sync(FULLMASK, v, 31);
        C = fmaf(g256, C, v31);

        curA = nxtA;
        curB = nxtB;
    }
}

extern "C" void kernel_launch(void* const* d_in, const int* in_sizes, int n_in,
                              void* d_out, int out_size)
{
    const float* x = (const float*)d_in[0];
    const float* w = (const float*)d_in[1];
    float* out = (float*)d_out;

    const int Cdim  = in_sizes[1];          // 512
    const int T     = 16384;                // fixed problem shape
    const int nrows = in_sizes[0] / T;      // B*C = 4096
    const int nseg  = T / 4096;             // 4 segments per row

    const int total_warps     = nrows * nseg;
    const int warps_per_block = 8;
    dim3 block(32 * warps_per_block);
    dim3 grid((total_warps + warps_per_block - 1) / warps_per_block);
    ema_scan_seg256_kernel<<<grid, block>>>(x, w, out, Cdim, T, nrows, nseg);
}